// round 1
// baseline (speedup 1.0000x reference)
#include <cuda_runtime.h>
#include <math.h>

// CropAndResize: x [B,H,W,C=4] fp32, boxes [B,4] (y1,x1,y2,x2 in [0,1]),
// output [B,crop,crop,4] fp32 bilinear crop-and-resize.
//
// One thread per output pixel; each thread gathers 4 corner float4s and
// writes one float4. Stores are fully coalesced (consecutive threads ->
// consecutive 16B). Boxes are tiny and L1-resident.

__global__ __launch_bounds__(256)
void crop_resize_kernel(const float* __restrict__ x,
                        const float* __restrict__ boxes,
                        float* __restrict__ out,
                        int H, int W, int crop) {
    const int b   = blockIdx.y;
    const int idx = blockIdx.x * blockDim.x + threadIdx.x;
    const int npx = crop * crop;
    if (idx >= npx) return;

    const int row = idx / crop;   // output y
    const int col = idx - row * crop;  // output x

    // Box params (L1-cached broadcast)
    const float y1 = __ldg(&boxes[b * 4 + 0]);
    const float x1 = __ldg(&boxes[b * 4 + 1]);
    const float y2 = __ldg(&boxes[b * 4 + 2]);
    const float x2 = __ldg(&boxes[b * 4 + 3]);

    const float inv = 1.0f / (float)(crop - 1);
    const float gy = (float)row * inv;
    const float gx = (float)col * inv;

    const float in_y = (y1 + gy * (y2 - y1)) * (float)(H - 1);
    const float in_x = (x1 + gx * (x2 - x1)) * (float)(W - 1);

    const bool valid = (in_y >= 0.0f) && (in_y <= (float)(H - 1)) &&
                       (in_x >= 0.0f) && (in_x <= (float)(W - 1));

    float4 result = make_float4(0.f, 0.f, 0.f, 0.f);

    if (valid) {
        const float top_f  = floorf(in_y);
        const float left_f = floorf(in_x);
        const float yl = in_y - top_f;
        const float xl = in_x - left_f;

        int t = (int)top_f;  t = min(max(t, 0), H - 1);
        int bo = min(t + 1, H - 1);
        int l = (int)left_f; l = min(max(l, 0), W - 1);
        int r = min(l + 1, W - 1);

        const float4* xb = (const float4*)(x) + (size_t)b * H * W;
        const float4 tl = __ldg(xb + (size_t)t  * W + l);
        const float4 tr = __ldg(xb + (size_t)t  * W + r);
        const float4 bl = __ldg(xb + (size_t)bo * W + l);
        const float4 br = __ldg(xb + (size_t)bo * W + r);

        // top = tl + (tr-tl)*xl ; bot = bl + (br-bl)*xl ; out = top + (bot-top)*yl
        float4 top_i, bot_i;
        top_i.x = tl.x + (tr.x - tl.x) * xl;
        top_i.y = tl.y + (tr.y - tl.y) * xl;
        top_i.z = tl.z + (tr.z - tl.z) * xl;
        top_i.w = tl.w + (tr.w - tl.w) * xl;
        bot_i.x = bl.x + (br.x - bl.x) * xl;
        bot_i.y = bl.y + (br.y - bl.y) * xl;
        bot_i.z = bl.z + (br.z - bl.z) * xl;
        bot_i.w = bl.w + (br.w - bl.w) * xl;
        result.x = top_i.x + (bot_i.x - top_i.x) * yl;
        result.y = top_i.y + (bot_i.y - top_i.y) * yl;
        result.z = top_i.z + (bot_i.z - top_i.z) * yl;
        result.w = top_i.w + (bot_i.w - top_i.w) * yl;
    }

    float4* outb = (float4*)(out) + (size_t)b * npx;
    outb[idx] = result;
}

extern "C" void kernel_launch(void* const* d_in, const int* in_sizes, int n_in,
                              void* d_out, int out_size) {
    const float* x     = (const float*)d_in[0];
    const float* boxes = (const float*)d_in[1];
    float* out = (float*)d_out;

    const int B = in_sizes[1] / 4;          // boxes is [B,4]
    const int C = 4;
    // x is [B,H,W,C] with H==W
    const long long hw = (long long)in_sizes[0] / ((long long)B * C);
    int H = (int)(sqrt((double)hw) + 0.5);
    int W = H;
    // out is [B,crop,crop,C]
    const long long cc = (long long)out_size / ((long long)B * C);
    int crop = (int)(sqrt((double)cc) + 0.5);

    const int npx = crop * crop;
    dim3 block(256);
    dim3 grid((npx + 255) / 256, B);
    crop_resize_kernel<<<grid, block>>>(x, boxes, out, H, W, crop);
}